// round 11
// baseline (speedup 1.0000x reference)
#include <cuda_runtime.h>
#include <cuda_bf16.h>
#include <math.h>

typedef unsigned long long ull;

// Problem constants
#define BT   256
#define TT   250
#define II   700
#define HH   128
#define OO   20
#define B_J0 0.01f
#define BETA 1.8f

// Output layout: output[256*20], s1[256*128], s2[256*128], A_norm[1]
#define OUT_OFF_ACC  0
#define OUT_OFF_S1   (BT*OO)
#define OUT_OFF_S2   (OUT_OFF_S1 + BT*HH)
#define OUT_OFF_NORM (OUT_OFF_S2 + BT*HH)

// Static device scratch (no allocations allowed)
__device__ float g_xin[TT * BT * HH];   // 32 MB
__device__ float g_om[TT * BT * OO];    // 5.12 MB
__device__ float g_npart[64];

// ---------------------------------------------------------------------------
// f32x2 helpers
// ---------------------------------------------------------------------------
__device__ __forceinline__ ull ffma2(ull a, ull b, ull c)
{
    ull d;
    asm("fma.rn.f32x2 %0, %1, %2, %3;" : "=l"(d) : "l"(a), "l"(b), "l"(c));
    return d;
}
__device__ __forceinline__ ull add2(ull a, ull b)
{
    ull d;
    asm("add.rn.f32x2 %0, %1, %2;" : "=l"(d) : "l"(a), "l"(b));
    return d;
}
__device__ __forceinline__ ull pack2(float lo, float hi)
{
    ull d;
    asm("mov.b64 %0, {%1, %2};" : "=l"(d) : "f"(lo), "f"(hi));
    return d;
}
__device__ __forceinline__ float2 unpack2(ull v)
{
    float lo, hi;
    asm("mov.b64 {%0, %1}, %2;" : "=f"(lo), "=f"(hi) : "l"(v));
    return make_float2(lo, hi);
}

// ---------------------------------------------------------------------------
// Kernel 1: xin GEMM (128x128 tile, FFMA2, bit-exact; unchanged)
// ---------------------------------------------------------------------------
#define GTM 128
#define KT  8
#define NKTILE ((II + KT - 1) / KT)   // 88

__global__ __launch_bounds__(256, 2) void gemm_xin_kernel(
    const float* __restrict__ x,
    const float* __restrict__ w,
    const float* __restrict__ bias,
    float* __restrict__ xin)
{
    __shared__ float As[2][KT][GTM];
    __shared__ float Bs[2][KT][HH];

    const int tid = threadIdx.x;
    const int tx = tid & 15;
    const int ty = tid >> 4;
    const int bm = blockIdx.x * GTM;
    const int n0 = tx * 8;
    const int m0 = ty * 8;

    ull acc[4][8];
#pragma unroll
    for (int p = 0; p < 4; p++)
#pragma unroll
        for (int j = 0; j < 8; j++) acc[p][j] = 0ull;

    const int la_m = tid & 127;
    const int la_k = (tid >> 7) * 4;
    const float* xrow = x + (size_t)(bm + la_m) * II + la_k;
    const int bk = tid >> 5;
    const int bn = (tid & 31) * 4;

    {
        float4 av = *(const float4*)(xrow);
        float4 bv = *(const float4*)(w + (size_t)bk * HH + bn);
        As[0][la_k + 0][la_m] = av.x;
        As[0][la_k + 1][la_m] = av.y;
        As[0][la_k + 2][la_m] = av.z;
        As[0][la_k + 3][la_m] = av.w;
        *(float4*)&Bs[0][bk][bn] = bv;
    }
    __syncthreads();

    for (int tI = 0; tI < NKTILE; tI++) {
        const int buf = tI & 1;
        float4 nav, nbv;
        const bool has = (tI + 1 < NKTILE);
        if (has) {
            int k0 = (tI + 1) * KT;
            nav = (k0 + la_k + 3 < II) ? *(const float4*)(xrow + k0)
                                       : make_float4(0.f, 0.f, 0.f, 0.f);
            int kk = k0 + bk;
            nbv = (kk < II) ? *(const float4*)(w + (size_t)kk * HH + bn)
                            : make_float4(0.f, 0.f, 0.f, 0.f);
        }

#pragma unroll
        for (int k = 0; k < KT; k++) {
            ull a[4];
            const ulonglong2* Ap = (const ulonglong2*)&As[buf][k][m0];
            ulonglong2 av;
            av = Ap[0]; a[0] = av.x; a[1] = av.y;
            av = Ap[1]; a[2] = av.x; a[3] = av.y;
            float4 b0 = *(const float4*)&Bs[buf][k][n0];
            float4 b1 = *(const float4*)&Bs[buf][k][n0 + 4];
            float bj[8] = {b0.x, b0.y, b0.z, b0.w, b1.x, b1.y, b1.z, b1.w};
#pragma unroll
            for (int j = 0; j < 8; j++) {
                ull bb = pack2(bj[j], bj[j]);
#pragma unroll
                for (int p = 0; p < 4; p++)
                    acc[p][j] = ffma2(a[p], bb, acc[p][j]);
            }
        }

        if (has) {
            int nb = buf ^ 1;
            As[nb][la_k + 0][la_m] = nav.x;
            As[nb][la_k + 1][la_m] = nav.y;
            As[nb][la_k + 2][la_m] = nav.z;
            As[nb][la_k + 3][la_m] = nav.w;
            *(float4*)&Bs[nb][bk][bn] = nbv;
        }
        __syncthreads();
    }

    float bn8[8];
#pragma unroll
    for (int j = 0; j < 8; j++) bn8[j] = bias[n0 + j];

#pragma unroll
    for (int p = 0; p < 4; p++) {
        float lo[8], hi[8];
#pragma unroll
        for (int j = 0; j < 8; j++) {
            float2 v = unpack2(acc[p][j]);
            lo[j] = v.x; hi[j] = v.y;
        }
        int mg = bm + m0 + 2 * p;
#pragma unroll
        for (int half = 0; half < 2; half++) {
            const float* vv = half ? hi : lo;
            int m = mg + half;
            int bb = m / TT;
            int tt = m - bb * TT;
            float* op = xin + ((size_t)tt * BT + bb) * HH + n0;
            float4 v0, v1;
            v0.x = __fadd_rn(vv[0], bn8[0]);
            v0.y = __fadd_rn(vv[1], bn8[1]);
            v0.z = __fadd_rn(vv[2], bn8[2]);
            v0.w = __fadd_rn(vv[3], bn8[3]);
            v1.x = __fadd_rn(vv[4], bn8[4]);
            v1.y = __fadd_rn(vv[5], bn8[5]);
            v1.z = __fadd_rn(vv[6], bn8[6]);
            v1.w = __fadd_rn(vv[7], bn8[7]);
            *(float4*)(op)     = v0;
            *(float4*)(op + 4) = v1;
        }
    }
}

// ---------------------------------------------------------------------------
// Paired dual gather (f32x2 lanes, ascending order, bit-identical per column)
// ---------------------------------------------------------------------------
template<int SB>
__device__ __forceinline__ void dual_gather2(const float* __restrict__ wa,
                                             const float* __restrict__ wb,
                                             const int* __restrict__ lst,
                                             int cpad, int ea, int eb,
                                             ull& qa, ull& qb)
{
    ull A = 0ull, B = 0ull;
    int nb = cpad >> 2;
    if (nb) {
        const int4* L = (const int4*)lst;
        int4 id = L[0];
        ull a0 = *(const ull*)(wa + (id.x << 7) + ea);
        ull a1 = *(const ull*)(wa + (id.y << 7) + ea);
        ull a2 = *(const ull*)(wa + (id.z << 7) + ea);
        ull a3 = *(const ull*)(wa + (id.w << 7) + ea);
        ull b0 = *(const ull*)(wb + id.x * SB + eb);
        ull b1 = *(const ull*)(wb + id.y * SB + eb);
        ull b2 = *(const ull*)(wb + id.z * SB + eb);
        ull b3 = *(const ull*)(wb + id.w * SB + eb);
        for (int i = 1; i < nb; i++) {
            int4 idn = L[i];
            ull na0 = *(const ull*)(wa + (idn.x << 7) + ea);
            ull na1 = *(const ull*)(wa + (idn.y << 7) + ea);
            ull na2 = *(const ull*)(wa + (idn.z << 7) + ea);
            ull na3 = *(const ull*)(wa + (idn.w << 7) + ea);
            ull nb0 = *(const ull*)(wb + idn.x * SB + eb);
            ull nb1 = *(const ull*)(wb + idn.y * SB + eb);
            ull nb2 = *(const ull*)(wb + idn.z * SB + eb);
            ull nb3 = *(const ull*)(wb + idn.w * SB + eb);
            A = add2(A, a0); B = add2(B, b0);
            A = add2(A, a1); B = add2(B, b1);
            A = add2(A, a2); B = add2(B, b2);
            A = add2(A, a3); B = add2(B, b3);
            a0 = na0; a1 = na1; a2 = na2; a3 = na3;
            b0 = nb0; b1 = nb1; b2 = nb2; b3 = nb3;
        }
        A = add2(A, a0); B = add2(B, b0);
        A = add2(A, a1); B = add2(B, b1);
        A = add2(A, a2); B = add2(B, b2);
        A = add2(A, a3); B = add2(B, b3);
    }
    qa = A; qb = B;
}

__device__ __forceinline__ float decay(float tau)
{
    float u = __fdiv_rn(-1.0f, tau);
    return (float)exp((double)u);
}

// ---------------------------------------------------------------------------
// Kernel 2: the scan. 64 CTAs x 256 threads; 4 batch rows per CTA
// (r = tid>>6, 2 warps per row => 2 warps per SMSP for latency hiding).
// Thread l = tid&63 owns h-pair {2l, 2l+1}. Paired f32x2 body (R10).
// Named 64-thread barriers per row (barid 1..4).
// ---------------------------------------------------------------------------
#define ROWS_PER_CTA 4
#define WROW 129
#define SCAN_SMEM_BYTES ((WROW*128*3 + WROW*20)*4 + (ROWS_PER_CTA*128*2)*4 + 256)

__global__ __launch_bounds__(256, 1) void scan_kernel(
    const float* __restrict__ xin,
    const float* __restrict__ mask,
    const float* __restrict__ w_h1h1, const float* __restrict__ b_h1h1,
    const float* __restrict__ w_h1h2, const float* __restrict__ b_h1h2,
    const float* __restrict__ w_h2h2, const float* __restrict__ b_h2h2,
    const float* __restrict__ w_h2o,  const float* __restrict__ b_h2o,
    const float* __restrict__ tau_adp_h1, const float* __restrict__ tau_adp_h2,
    const float* __restrict__ tau_m_h1,   const float* __restrict__ tau_m_h2,
    const float* __restrict__ tau_m_o,
    const float* __restrict__ hid1_mem0,  const float* __restrict__ hid2_mem0,
    const float* __restrict__ out_mem0,
    float* __restrict__ om_out,
    float* __restrict__ out)
{
    extern __shared__ unsigned char smraw[];
    float* w11s = (float*)smraw;                 // 129*128 (masked, zero pad row)
    float* w12s = w11s + WROW * 128;             // 129*128
    float* w22s = w12s + WROW * 128;             // 129*128
    float* w2os = w22s + WROW * 128;             // 129*20
    int*   list1 = (int*)(w2os + WROW * 20);     // [4][128]
    int*   list2 = list1 + ROWS_PER_CTA * 128;   // [4][128]
    unsigned* m1s = (unsigned*)(list2 + ROWS_PER_CTA * 128); // [4][4]
    unsigned* m2s = m1s + 16;                                // [4][4]

    const int tid  = threadIdx.x;
    const int r    = tid >> 6;        // row within CTA (0..3)
    const int l    = tid & 63;        // h-pair index
    const int wrow = l >> 5;          // warp within row (0,1)
    const int lane = tid & 31;
    const int grow = blockIdx.x * ROWS_PER_CTA + r;
    const int barid = 1 + r;
    const int h0 = 2 * l;

    // ---- load weights (masked) + zero pad rows ----
    for (int i = tid; i < 16384; i += 256) {
        w11s[i] = __fmul_rn(w_h1h1[i], mask[i]);
        w12s[i] = w_h1h2[i];
        w22s[i] = __fmul_rn(w_h2h2[i], mask[16384 + i]);
    }
    for (int i = tid; i < 2560; i += 256) w2os[i] = w_h2o[i];
    if (tid < 128) {
        w11s[16384 + tid] = 0.f;
        w12s[16384 + tid] = 0.f;
        w22s[16384 + tid] = 0.f;
    }
    if (tid < 20) w2os[2560 + tid] = 0.f;

    // ---- per-thread parameters & state (2 h each) ----
    float a1[2], r1[2], a2[2], r2[2], oma1[2], omr1[2], oma2[2], omr2[2];
    float b11r[2], b12a[2], b12b[2];
    float h1m[2], h2m[2], b1[2], b2[2], h1sp[2], h2sp[2], s1c[2], s2c[2];
#pragma unroll
    for (int j = 0; j < 2; j++) {
        int h = h0 + j;
        a1[j] = decay(tau_m_h1[h]);
        r1[j] = decay(tau_adp_h1[h]);
        a2[j] = decay(tau_m_h2[h]);
        r2[j] = decay(tau_adp_h2[h]);
        oma1[j] = __fsub_rn(1.0f, a1[j]);
        omr1[j] = __fsub_rn(1.0f, r1[j]);
        oma2[j] = __fsub_rn(1.0f, a2[j]);
        omr2[j] = __fsub_rn(1.0f, r2[j]);
        b11r[j] = b_h1h1[h];
        b12a[j] = b_h1h2[h];
        b12b[j] = b_h2h2[h];
        h1m[j] = hid1_mem0[grow * HH + h];
        h2m[j] = hid2_mem0[grow * HH + h];
        b1[j] = B_J0; b2[j] = B_J0;
        h1sp[j] = 0.f; h2sp[j] = 0.f;
        s1c[j] = 0.f; s2c[j] = 0.f;
    }
    ull d11 = 0ull, d22 = 0ull;

    const bool ro = (l < 10);
    const int eo = ro ? h0 : 0;
    float om[2] = {0.f, 0.f}, aoo[2] = {0.f, 0.f}, omao[2] = {0.f, 0.f}, bo[2] = {0.f, 0.f};
    if (ro) {
#pragma unroll
        for (int j = 0; j < 2; j++) {
            om[j]   = out_mem0[grow * OO + h0 + j];
            aoo[j]  = decay(tau_m_o[h0 + j]);
            omao[j] = __fsub_rn(1.0f, aoo[j]);
            bo[j]   = b_h2o[h0 + j];
        }
    }
    __syncthreads();

    float2 xt = *(const float2*)&xin[((size_t)0 * BT + grow) * HH + h0];

    for (int t = 0; t < TT; t++) {
        float2 xnext = make_float2(0.f, 0.f);
        if (t + 1 < TT)
            xnext = __ldg((const float2*)&xin[((size_t)(t + 1) * BT + grow) * HH + h0]);

        // ---- layer 1 (d11 hoisted) ----
        float2 d11f = unpack2(d11);
        float d11a[2] = {d11f.x, d11f.y};
        float xta[2] = {xt.x, xt.y};
        float sp1[2];
#pragma unroll
        for (int j = 0; j < 2; j++) {
            float i1 = __fadd_rn(__fadd_rn(xta[j], d11a[j]), b11r[j]);
            b1[j] = __fadd_rn(__fmul_rn(r1[j], b1[j]), __fmul_rn(omr1[j], h1sp[j]));
            float B1 = __fadd_rn(B_J0, __fmul_rn(BETA, b1[j]));
            h1m[j] = __fsub_rn(__fadd_rn(__fmul_rn(h1m[j], a1[j]), __fmul_rn(oma1[j], i1)),
                               __fmul_rn(B1, h1sp[j]));
            sp1[j] = (__fsub_rn(h1m[j], B1) > 0.0f) ? 1.0f : 0.0f;
            s1c[j] += sp1[j];
        }

        unsigned E = __ballot_sync(0xffffffffu, sp1[0] != 0.0f);
        unsigned Od = __ballot_sync(0xffffffffu, sp1[1] != 0.0f);
        if (lane == 0) { m1s[r * 4 + wrow * 2] = E; m1s[r * 4 + wrow * 2 + 1] = Od; }
        asm volatile("bar.sync %0, 64;" :: "r"(barid) : "memory");   // B1

        unsigned E0 = m1s[r * 4 + 0], O0 = m1s[r * 4 + 1];
        unsigned E1 = m1s[r * 4 + 2], O1 = m1s[r * 4 + 3];
        int c1 = __popc(E0) + __popc(O0) + __popc(E1) + __popc(O1);
        int c1np = (c1 + 3) & ~3;
        {
            int* Lr = list1 + (r << 7);
            int base = wrow ? (__popc(E0) + __popc(O0)) : 0;
            unsigned below = (1u << lane) - 1u;
            int rk = base + __popc(E & below) + __popc(Od & below);
            if (sp1[0] != 0.0f) Lr[rk] = h0;
            if (sp1[1] != 0.0f) Lr[rk + (int)((E >> lane) & 1u)] = h0 + 1;
            if (l >= c1 && l < c1np) Lr[l] = 128;
            if (l + 64 >= c1 && l + 64 < c1np) Lr[l + 64] = 128;
        }
        asm volatile("bar.sync %0, 64;" :: "r"(barid) : "memory");   // B2

        // ---- dual gather: d12(t) and d11(t+1) over list1 ----
        ull d12p, d11n;
        dual_gather2<128>(w12s, w11s, list1 + (r << 7), c1np, h0, h0, d12p, d11n);

        // ---- layer 2 (d22 hoisted) ----
        float2 d12f = unpack2(d12p);
        float2 d22f = unpack2(d22);
        float d12a[2] = {d12f.x, d12f.y};
        float d22a[2] = {d22f.x, d22f.y};
        float sp2[2];
#pragma unroll
        for (int j = 0; j < 2; j++) {
            float i2 = __fadd_rn(__fadd_rn(__fadd_rn(d12a[j], b12a[j]), d22a[j]), b12b[j]);
            b2[j] = __fadd_rn(__fmul_rn(r2[j], b2[j]), __fmul_rn(omr2[j], h2sp[j]));
            float B2 = __fadd_rn(B_J0, __fmul_rn(BETA, b2[j]));
            h2m[j] = __fsub_rn(__fadd_rn(__fmul_rn(h2m[j], a2[j]), __fmul_rn(oma2[j], i2)),
                               __fmul_rn(B2, h2sp[j]));
            sp2[j] = (__fsub_rn(h2m[j], B2) > 0.0f) ? 1.0f : 0.0f;
            s2c[j] += sp2[j];
        }

        unsigned F = __ballot_sync(0xffffffffu, sp2[0] != 0.0f);
        unsigned P = __ballot_sync(0xffffffffu, sp2[1] != 0.0f);
        if (lane == 0) { m2s[r * 4 + wrow * 2] = F; m2s[r * 4 + wrow * 2 + 1] = P; }
        asm volatile("bar.sync %0, 64;" :: "r"(barid) : "memory");   // B3

        unsigned F0 = m2s[r * 4 + 0], P0 = m2s[r * 4 + 1];
        unsigned F1 = m2s[r * 4 + 2], P1 = m2s[r * 4 + 3];
        int c2 = __popc(F0) + __popc(P0) + __popc(F1) + __popc(P1);
        int c2np = (c2 + 3) & ~3;
        {
            int* Lr = list2 + (r << 7);
            int base = wrow ? (__popc(F0) + __popc(P0)) : 0;
            unsigned below = (1u << lane) - 1u;
            int rk = base + __popc(F & below) + __popc(P & below);
            if (sp2[0] != 0.0f) Lr[rk] = h0;
            if (sp2[1] != 0.0f) Lr[rk + (int)((F >> lane) & 1u)] = h0 + 1;
            if (l >= c2 && l < c2np) Lr[l] = 128;
            if (l + 64 >= c2 && l + 64 < c2np) Lr[l + 64] = 128;
        }
        asm volatile("bar.sync %0, 64;" :: "r"(barid) : "memory");   // B4

        // ---- dual gather: d22(t+1) and d2o(t) over list2 ----
        ull d22n, d2op;
        dual_gather2<20>(w22s, w2os, list2 + (r << 7), c2np, h0, eo, d22n, d2op);

        // ---- readout om update (softmax deferred) ----
        if (ro) {
            float2 d2of = unpack2(d2op);
            float d2oa[2] = {d2of.x, d2of.y};
#pragma unroll
            for (int j = 0; j < 2; j++) {
                float io = __fadd_rn(d2oa[j], bo[j]);
                om[j] = __fadd_rn(__fmul_rn(om[j], aoo[j]), __fmul_rn(omao[j], io));
            }
            *(float2*)&om_out[((size_t)t * BT + grow) * OO + h0] = make_float2(om[0], om[1]);
        }

#pragma unroll
        for (int j = 0; j < 2; j++) { h1sp[j] = sp1[j]; h2sp[j] = sp2[j]; }
        d11 = d11n;
        d22 = d22n;
        xt = xnext;
    }

    *(float2*)&out[OUT_OFF_S1 + grow * HH + h0] =
        make_float2(__fdiv_rn(s1c[0], (float)TT), __fdiv_rn(s1c[1], (float)TT));
    *(float2*)&out[OUT_OFF_S2 + grow * HH + h0] =
        make_float2(__fdiv_rn(s2c[0], (float)TT), __fdiv_rn(s2c[1], (float)TT));
}

// ---------------------------------------------------------------------------
// Kernel 2b: softmax + ascending-t accumulation per batch row.
// ---------------------------------------------------------------------------
__global__ __launch_bounds__(256) void softmax_acc_kernel(
    const float* __restrict__ om_in, float* __restrict__ out)
{
    __shared__ float sm[(TT - 11) * OO];
    const int b = blockIdx.x;
    const int wid = threadIdx.x >> 5;
    const int lane = threadIdx.x & 31;

    for (int t = 11 + wid; t < TT; t += 8) {
        float om = (lane < OO) ? om_in[((size_t)t * BT + b) * OO + lane] : 0.f;
        float v = (lane < OO) ? om : -3.4e38f;
#pragma unroll
        for (int d = 16; d; d >>= 1) v = fmaxf(v, __shfl_xor_sync(0xffffffffu, v, d));
        float e = (lane < OO) ? expf(__fsub_rn(om, v)) : 0.f;
        float ssum = e;
#pragma unroll
        for (int d = 16; d; d >>= 1) ssum += __shfl_xor_sync(0xffffffffu, ssum, d);
        if (lane < OO) sm[(t - 11) * OO + lane] = __fdiv_rn(e, ssum);
    }
    __syncthreads();

    if (threadIdx.x < OO) {
        float a = 0.f;
        for (int tt = 0; tt < TT - 11; tt++)
            a = __fadd_rn(a, sm[tt * OO + threadIdx.x]);
        out[OUT_OFF_ACC + b * OO + threadIdx.x] = a;
    }
}

// ---------------------------------------------------------------------------
// Kernel 3a/3b: A_norm (deterministic two-pass)
// ---------------------------------------------------------------------------
__global__ __launch_bounds__(256) void norm_part_kernel(
    const float* __restrict__ w11, const float* __restrict__ w22,
    const float* __restrict__ mask)
{
    __shared__ float red[256];
    int i = blockIdx.x * 256 + threadIdx.x;
    float s = fabsf(__fmul_rn(w11[i], mask[i]))
            + fabsf(__fmul_rn(w22[i], mask[16384 + i]));
    red[threadIdx.x] = s;
    __syncthreads();
    for (int d = 128; d > 0; d >>= 1) {
        if (threadIdx.x < d) red[threadIdx.x] += red[threadIdx.x + d];
        __syncthreads();
    }
    if (threadIdx.x == 0) g_npart[blockIdx.x] = red[0];
}

__global__ void norm_finish_kernel(float* __restrict__ out)
{
    int lane = threadIdx.x;
    __shared__ float w[2];
    float s = g_npart[lane];
#pragma unroll
    for (int d = 16; d; d >>= 1) s += __shfl_xor_sync(0xffffffffu, s, d);
    if ((lane & 31) == 0) w[lane >> 5] = s;
    __syncthreads();
    if (lane == 0) out[OUT_OFF_NORM] = w[0] + w[1];
}

// ---------------------------------------------------------------------------
extern "C" void kernel_launch(void* const* d_in, const int* in_sizes, int n_in,
                              void* d_out, int out_size)
{
    const float* x          = (const float*)d_in[0];
    const float* mask       = (const float*)d_in[1];
    const float* w_ih1      = (const float*)d_in[2];
    const float* b_ih1      = (const float*)d_in[3];
    const float* w_h1h1     = (const float*)d_in[4];
    const float* b_h1h1     = (const float*)d_in[5];
    const float* w_h1h2     = (const float*)d_in[6];
    const float* b_h1h2     = (const float*)d_in[7];
    const float* w_h2h2     = (const float*)d_in[8];
    const float* b_h2h2     = (const float*)d_in[9];
    const float* w_h2o      = (const float*)d_in[10];
    const float* b_h2o      = (const float*)d_in[11];
    const float* tau_adp_h1 = (const float*)d_in[12];
    const float* tau_adp_h2 = (const float*)d_in[13];
    const float* tau_m_h1   = (const float*)d_in[14];
    const float* tau_m_h2   = (const float*)d_in[15];
    const float* tau_m_o    = (const float*)d_in[16];
    const float* hid1_mem0  = (const float*)d_in[17];
    const float* hid2_mem0  = (const float*)d_in[18];
    const float* out_mem0   = (const float*)d_in[19];
    float* out = (float*)d_out;

    float* xin = nullptr;
    cudaGetSymbolAddress((void**)&xin, g_xin);
    float* omb = nullptr;
    cudaGetSymbolAddress((void**)&omb, g_om);

    cudaFuncSetAttribute(scan_kernel, cudaFuncAttributeMaxDynamicSharedMemorySize,
                         SCAN_SMEM_BYTES);

    gemm_xin_kernel<<<(BT * TT) / GTM, 256>>>(x, w_ih1, b_ih1, xin);
    scan_kernel<<<BT / ROWS_PER_CTA, 256, SCAN_SMEM_BYTES>>>(
        xin, mask, w_h1h1, b_h1h1, w_h1h2, b_h1h2, w_h2h2, b_h2h2,
        w_h2o, b_h2o, tau_adp_h1, tau_adp_h2, tau_m_h1, tau_m_h2, tau_m_o,
        hid1_mem0, hid2_mem0, out_mem0, omb, out);
    softmax_acc_kernel<<<BT, 256>>>(omb, out);
    norm_part_kernel<<<64, 256>>>(w_h1h1, w_h2h2, mask);
    norm_finish_kernel<<<1, 64>>>(out);
}

// round 14
// speedup vs baseline: 1.0060x; 1.0060x over previous
#include <cuda_runtime.h>
#include <cuda_bf16.h>
#include <math.h>

typedef unsigned long long ull;

// Problem constants
#define BT   256
#define TT   250
#define II   700
#define HH   128
#define OO   20
#define B_J0 0.01f
#define BETA 1.8f

// Output layout: output[256*20], s1[256*128], s2[256*128], A_norm[1]
#define OUT_OFF_ACC  0
#define OUT_OFF_S1   (BT*OO)
#define OUT_OFF_S2   (OUT_OFF_S1 + BT*HH)
#define OUT_OFF_NORM (OUT_OFF_S2 + BT*HH)

// Static device scratch (no allocations allowed)
__device__ float g_xin[TT * BT * HH];   // 32 MB
__device__ float g_om[TT * BT * OO];    // 5.12 MB
__device__ float g_npart[64];

// ---------------------------------------------------------------------------
// f32x2 helpers
// ---------------------------------------------------------------------------
__device__ __forceinline__ ull ffma2(ull a, ull b, ull c)
{
    ull d;
    asm("fma.rn.f32x2 %0, %1, %2, %3;" : "=l"(d) : "l"(a), "l"(b), "l"(c));
    return d;
}
__device__ __forceinline__ ull add2(ull a, ull b)
{
    ull d;
    asm("add.rn.f32x2 %0, %1, %2;" : "=l"(d) : "l"(a), "l"(b));
    return d;
}
__device__ __forceinline__ ull pack2(float lo, float hi)
{
    ull d;
    asm("mov.b64 %0, {%1, %2};" : "=l"(d) : "f"(lo), "f"(hi));
    return d;
}
__device__ __forceinline__ float2 unpack2(ull v)
{
    float lo, hi;
    asm("mov.b64 {%0, %1}, %2;" : "=f"(lo), "=f"(hi) : "l"(v));
    return make_float2(lo, hi);
}

// ---------------------------------------------------------------------------
// Kernel 1: xin GEMM (128x128 tile, FFMA2, bit-exact; unchanged)
// ---------------------------------------------------------------------------
#define GTM 128
#define KT  8
#define NKTILE ((II + KT - 1) / KT)   // 88

__global__ __launch_bounds__(256, 2) void gemm_xin_kernel(
    const float* __restrict__ x,
    const float* __restrict__ w,
    const float* __restrict__ bias,
    float* __restrict__ xin)
{
    __shared__ float As[2][KT][GTM];
    __shared__ float Bs[2][KT][HH];

    const int tid = threadIdx.x;
    const int tx = tid & 15;
    const int ty = tid >> 4;
    const int bm = blockIdx.x * GTM;
    const int n0 = tx * 8;
    const int m0 = ty * 8;

    ull acc[4][8];
#pragma unroll
    for (int p = 0; p < 4; p++)
#pragma unroll
        for (int j = 0; j < 8; j++) acc[p][j] = 0ull;

    const int la_m = tid & 127;
    const int la_k = (tid >> 7) * 4;
    const float* xrow = x + (size_t)(bm + la_m) * II + la_k;
    const int bk = tid >> 5;
    const int bn = (tid & 31) * 4;

    {
        float4 av = *(const float4*)(xrow);
        float4 bv = *(const float4*)(w + (size_t)bk * HH + bn);
        As[0][la_k + 0][la_m] = av.x;
        As[0][la_k + 1][la_m] = av.y;
        As[0][la_k + 2][la_m] = av.z;
        As[0][la_k + 3][la_m] = av.w;
        *(float4*)&Bs[0][bk][bn] = bv;
    }
    __syncthreads();

    for (int tI = 0; tI < NKTILE; tI++) {
        const int buf = tI & 1;
        float4 nav, nbv;
        const bool has = (tI + 1 < NKTILE);
        if (has) {
            int k0 = (tI + 1) * KT;
            nav = (k0 + la_k + 3 < II) ? *(const float4*)(xrow + k0)
                                       : make_float4(0.f, 0.f, 0.f, 0.f);
            int kk = k0 + bk;
            nbv = (kk < II) ? *(const float4*)(w + (size_t)kk * HH + bn)
                            : make_float4(0.f, 0.f, 0.f, 0.f);
        }

#pragma unroll
        for (int k = 0; k < KT; k++) {
            ull a[4];
            const ulonglong2* Ap = (const ulonglong2*)&As[buf][k][m0];
            ulonglong2 av;
            av = Ap[0]; a[0] = av.x; a[1] = av.y;
            av = Ap[1]; a[2] = av.x; a[3] = av.y;
            float4 b0 = *(const float4*)&Bs[buf][k][n0];
            float4 b1 = *(const float4*)&Bs[buf][k][n0 + 4];
            float bj[8] = {b0.x, b0.y, b0.z, b0.w, b1.x, b1.y, b1.z, b1.w};
#pragma unroll
            for (int j = 0; j < 8; j++) {
                ull bb = pack2(bj[j], bj[j]);
#pragma unroll
                for (int p = 0; p < 4; p++)
                    acc[p][j] = ffma2(a[p], bb, acc[p][j]);
            }
        }

        if (has) {
            int nb = buf ^ 1;
            As[nb][la_k + 0][la_m] = nav.x;
            As[nb][la_k + 1][la_m] = nav.y;
            As[nb][la_k + 2][la_m] = nav.z;
            As[nb][la_k + 3][la_m] = nav.w;
            *(float4*)&Bs[nb][bk][bn] = nbv;
        }
        __syncthreads();
    }

    float bn8[8];
#pragma unroll
    for (int j = 0; j < 8; j++) bn8[j] = bias[n0 + j];

#pragma unroll
    for (int p = 0; p < 4; p++) {
        float lo[8], hi[8];
#pragma unroll
        for (int j = 0; j < 8; j++) {
            float2 v = unpack2(acc[p][j]);
            lo[j] = v.x; hi[j] = v.y;
        }
        int mg = bm + m0 + 2 * p;
#pragma unroll
        for (int half = 0; half < 2; half++) {
            const float* vv = half ? hi : lo;
            int m = mg + half;
            int bb = m / TT;
            int tt = m - bb * TT;
            float* op = xin + ((size_t)tt * BT + bb) * HH + n0;
            float4 v0, v1;
            v0.x = __fadd_rn(vv[0], bn8[0]);
            v0.y = __fadd_rn(vv[1], bn8[1]);
            v0.z = __fadd_rn(vv[2], bn8[2]);
            v0.w = __fadd_rn(vv[3], bn8[3]);
            v1.x = __fadd_rn(vv[4], bn8[4]);
            v1.y = __fadd_rn(vv[5], bn8[5]);
            v1.z = __fadd_rn(vv[6], bn8[6]);
            v1.w = __fadd_rn(vv[7], bn8[7]);
            *(float4*)(op)     = v0;
            *(float4*)(op + 4) = v1;
        }
    }
}

// ---------------------------------------------------------------------------
// Quad gathers over one padded ascending list (single warp per row).
// All accumulator chains: single accumulator, ascending order -> bit-exact.
// Pad index 128 hits appended zero rows (q + 0.0 exact).
// ---------------------------------------------------------------------------
__device__ __forceinline__ void gather_p1(const float* __restrict__ w12s,
                                          const float* __restrict__ w11s,
                                          const int* __restrict__ lst, int cpad,
                                          int h0, int h64,
                                          ull& q12a, ull& q12b, ull& q11a, ull& q11b)
{
    ull A = 0ull, B = 0ull, C = 0ull, D = 0ull;
    const int4* L = (const int4*)lst;
    const int nb = cpad >> 2;
    for (int i = 0; i < nb; i++) {
        int4 id = L[i];
        int r0 = id.x << 7, r1 = id.y << 7, r2 = id.z << 7, r3 = id.w << 7;
        ull a0 = *(const ull*)(w12s + r0 + h0),  a1 = *(const ull*)(w12s + r1 + h0);
        ull a2 = *(const ull*)(w12s + r2 + h0),  a3 = *(const ull*)(w12s + r3 + h0);
        ull b0 = *(const ull*)(w12s + r0 + h64), b1 = *(const ull*)(w12s + r1 + h64);
        ull b2 = *(const ull*)(w12s + r2 + h64), b3 = *(const ull*)(w12s + r3 + h64);
        ull c0 = *(const ull*)(w11s + r0 + h0),  c1 = *(const ull*)(w11s + r1 + h0);
        ull c2 = *(const ull*)(w11s + r2 + h0),  c3 = *(const ull*)(w11s + r3 + h0);
        ull d0 = *(const ull*)(w11s + r0 + h64), d1 = *(const ull*)(w11s + r1 + h64);
        ull d2 = *(const ull*)(w11s + r2 + h64), d3 = *(const ull*)(w11s + r3 + h64);
        A = add2(A, a0); B = add2(B, b0); C = add2(C, c0); D = add2(D, d0);
        A = add2(A, a1); B = add2(B, b1); C = add2(C, c1); D = add2(D, d1);
        A = add2(A, a2); B = add2(B, b2); C = add2(C, c2); D = add2(D, d2);
        A = add2(A, a3); B = add2(B, b3); C = add2(C, c3); D = add2(D, d3);
    }
    q12a = A; q12b = B; q11a = C; q11b = D;
}

__device__ __forceinline__ void gather_p2(const float* __restrict__ w22s,
                                          const float* __restrict__ w2os,
                                          const int* __restrict__ lst, int cpad,
                                          int h0, int h64, int oo,
                                          ull& q22a, ull& q22b, float& q2o)
{
    ull A = 0ull, B = 0ull;
    float C = 0.f;
    const int4* L = (const int4*)lst;
    const int nb = cpad >> 2;
    for (int i = 0; i < nb; i++) {
        int4 id = L[i];
        int r0 = id.x << 7, r1 = id.y << 7, r2 = id.z << 7, r3 = id.w << 7;
        ull a0 = *(const ull*)(w22s + r0 + h0),  a1 = *(const ull*)(w22s + r1 + h0);
        ull a2 = *(const ull*)(w22s + r2 + h0),  a3 = *(const ull*)(w22s + r3 + h0);
        ull b0 = *(const ull*)(w22s + r0 + h64), b1 = *(const ull*)(w22s + r1 + h64);
        ull b2 = *(const ull*)(w22s + r2 + h64), b3 = *(const ull*)(w22s + r3 + h64);
        float c0 = w2os[id.x * OO + oo], c1 = w2os[id.y * OO + oo];
        float c2 = w2os[id.z * OO + oo], c3 = w2os[id.w * OO + oo];
        A = add2(A, a0); B = add2(B, b0); C = __fadd_rn(C, c0);
        A = add2(A, a1); B = add2(B, b1); C = __fadd_rn(C, c1);
        A = add2(A, a2); B = add2(B, b2); C = __fadd_rn(C, c2);
        A = add2(A, a3); B = add2(B, b3); C = __fadd_rn(C, c3);
    }
    q22a = A; q22b = B; q2o = C;
}

__device__ __forceinline__ float decay(float tau)
{
    float u = __fdiv_rn(-1.0f, tau);
    return (float)exp((double)u);
}

// ---------------------------------------------------------------------------
// Kernel 2: the scan. 64 CTAs x 128 threads; ONE WARP PER BATCH ROW
// (warp w = row w, 1 warp per SMSP). Lane owns 4 h: {2L, 2L+1, 64+2L, 65+2L}
// (two contiguous f32x2 pairs). Spike exchange via ballots only; list build
// is warp-private (ballot -> rank -> STS -> __syncwarp). ZERO bar.syncs.
// ---------------------------------------------------------------------------
#define ROWS_PER_CTA 4
#define WROW 129
#define SCAN_SMEM_BYTES ((WROW*128*3 + WROW*20)*4 + (ROWS_PER_CTA*128*2)*4 + 128)

__global__ __launch_bounds__(128, 1) void scan_kernel(
    const float* __restrict__ xin,
    const float* __restrict__ mask,
    const float* __restrict__ w_h1h1, const float* __restrict__ b_h1h1,
    const float* __restrict__ w_h1h2, const float* __restrict__ b_h1h2,
    const float* __restrict__ w_h2h2, const float* __restrict__ b_h2h2,
    const float* __restrict__ w_h2o,  const float* __restrict__ b_h2o,
    const float* __restrict__ tau_adp_h1, const float* __restrict__ tau_adp_h2,
    const float* __restrict__ tau_m_h1,   const float* __restrict__ tau_m_h2,
    const float* __restrict__ tau_m_o,
    const float* __restrict__ hid1_mem0,  const float* __restrict__ hid2_mem0,
    const float* __restrict__ out_mem0,
    float* __restrict__ om_out,
    float* __restrict__ out)
{
    extern __shared__ unsigned char smraw[];
    float* w11s = (float*)smraw;                 // 129*128 (masked, zero pad row)
    float* w12s = w11s + WROW * 128;             // 129*128
    float* w22s = w12s + WROW * 128;             // 129*128
    float* w2os = w22s + WROW * 128;             // 129*20
    int*   list1 = (int*)(w2os + WROW * 20);     // [4][128]
    int*   list2 = list1 + ROWS_PER_CTA * 128;   // [4][128]

    const int tid  = threadIdx.x;
    const int wid  = tid >> 5;        // row within CTA (0..3)
    const int lane = tid & 31;
    const int grow = blockIdx.x * ROWS_PER_CTA + wid;
    const int h0   = 2 * lane;        // first pair
    const int h64  = 64 + 2 * lane;   // second pair

    // ---- load weights (masked) + zero pad rows ----
    for (int i = tid; i < 16384; i += 128) {
        w11s[i] = __fmul_rn(w_h1h1[i], mask[i]);
        w12s[i] = w_h1h2[i];
        w22s[i] = __fmul_rn(w_h2h2[i], mask[16384 + i]);
    }
    for (int i = tid; i < 2560; i += 128) w2os[i] = w_h2o[i];
    {
        w11s[16384 + tid] = 0.f;
        w12s[16384 + tid] = 0.f;
        w22s[16384 + tid] = 0.f;
    }
    if (tid < 20) w2os[2560 + tid] = 0.f;

    // ---- per-thread parameters & state (4 h slots) ----
    float a1[4], r1[4], a2[4], r2[4], oma1[4], omr1[4], oma2[4], omr2[4];
    float b11r[4], b12a[4], b12b[4];
    float h1m[4], h2m[4], b1[4], b2[4], h1sp[4], h2sp[4], s1c[4], s2c[4];
    const int hs[4] = {h0, h0 + 1, h64, h64 + 1};
#pragma unroll
    for (int j = 0; j < 4; j++) {
        int h = hs[j];
        a1[j] = decay(tau_m_h1[h]);
        r1[j] = decay(tau_adp_h1[h]);
        a2[j] = decay(tau_m_h2[h]);
        r2[j] = decay(tau_adp_h2[h]);
        oma1[j] = __fsub_rn(1.0f, a1[j]);
        omr1[j] = __fsub_rn(1.0f, r1[j]);
        oma2[j] = __fsub_rn(1.0f, a2[j]);
        omr2[j] = __fsub_rn(1.0f, r2[j]);
        b11r[j] = b_h1h1[h];
        b12a[j] = b_h1h2[h];
        b12b[j] = b_h2h2[h];
        h1m[j] = hid1_mem0[grow * HH + h];
        h2m[j] = hid2_mem0[grow * HH + h];
        b1[j] = B_J0; b2[j] = B_J0;
        h1sp[j] = 0.f; h2sp[j] = 0.f;
        s1c[j] = 0.f; s2c[j] = 0.f;
    }
    ull d11a = 0ull, d11b = 0ull, d22a = 0ull, d22b = 0ull;  // hoisted
    int c1p = 0, c2p = 0;

    // readout: lanes 0..19 own one output column each
    const bool ro = (lane < OO);
    const int oo = ro ? lane : 0;
    float om = 0.f, aoo = 0.f, omao = 0.f, bo = 0.f;
    if (ro) {
        om   = out_mem0[grow * OO + lane];
        aoo  = decay(tau_m_o[lane]);
        omao = __fsub_rn(1.0f, aoo);
        bo   = b_h2o[lane];
    }
    __syncthreads();   // weights visible to all 4 warps

    int* L1 = list1 + (wid << 7);
    int* L2 = list2 + (wid << 7);

    float2 xtA = *(const float2*)&xin[((size_t)0 * BT + grow) * HH + h0];
    float2 xtB = *(const float2*)&xin[((size_t)0 * BT + grow) * HH + h64];

    for (int t = 0; t < TT; t++) {
        float2 xnA = make_float2(0.f, 0.f), xnB = make_float2(0.f, 0.f);
        if (t + 1 < TT) {
            xnA = __ldg((const float2*)&xin[((size_t)(t + 1) * BT + grow) * HH + h0]);
            xnB = __ldg((const float2*)&xin[((size_t)(t + 1) * BT + grow) * HH + h64]);
        }

        // ---- layer 1 (d11 hoisted from previous step) ----
        float2 dA = unpack2(d11a), dB = unpack2(d11b);
        float d11v[4] = {dA.x, dA.y, dB.x, dB.y};
        float xtv[4] = {xtA.x, xtA.y, xtB.x, xtB.y};
        float sp1[4];
#pragma unroll
        for (int j = 0; j < 4; j++) {
            float i1 = __fadd_rn(__fadd_rn(xtv[j], d11v[j]), b11r[j]);
            b1[j] = __fadd_rn(__fmul_rn(r1[j], b1[j]), __fmul_rn(omr1[j], h1sp[j]));
            float B1 = __fadd_rn(B_J0, __fmul_rn(BETA, b1[j]));
            h1m[j] = __fsub_rn(__fadd_rn(__fmul_rn(h1m[j], a1[j]), __fmul_rn(oma1[j], i1)),
                               __fmul_rn(B1, h1sp[j]));
            sp1[j] = (__fsub_rn(h1m[j], B1) > 0.0f) ? 1.0f : 0.0f;
            s1c[j] += sp1[j];
        }

        // warp-private list build (ascending h): zero barriers
        unsigned E0 = __ballot_sync(0xffffffffu, sp1[0] != 0.0f);
        unsigned O0 = __ballot_sync(0xffffffffu, sp1[1] != 0.0f);
        unsigned E1 = __ballot_sync(0xffffffffu, sp1[2] != 0.0f);
        unsigned O1 = __ballot_sync(0xffffffffu, sp1[3] != 0.0f);
        {
            unsigned below = (1u << lane) - 1u;
            int base1 = __popc(E0) + __popc(O0);
            int c1 = base1 + __popc(E1) + __popc(O1);
            int c1np = (c1 + 3) & ~3;
            int rk0 = __popc(E0 & below) + __popc(O0 & below);
            int rk1 = rk0 + (int)((E0 >> lane) & 1u);
            int rk2 = base1 + __popc(E1 & below) + __popc(O1 & below);
            int rk3 = rk2 + (int)((E1 >> lane) & 1u);
            if (sp1[0] != 0.0f) L1[rk0] = h0;
            if (sp1[1] != 0.0f) L1[rk1] = h0 + 1;
            if (sp1[2] != 0.0f) L1[rk2] = h64;
            if (sp1[3] != 0.0f) L1[rk3] = h64 + 1;
            if (lane < c1np - c1) L1[c1 + lane] = 128;
            c1p = c1np;
        }
        __syncwarp();

        // ---- quad gather: d12(t) + d11(t+1) over list1 ----
        ull d12a, d12b, n11a, n11b;
        gather_p1(w12s, w11s, L1, c1p, h0, h64, d12a, d12b, n11a, n11b);

        // ---- layer 2 (d22 hoisted) ----
        float2 eA = unpack2(d12a), eB = unpack2(d12b);
        float2 fA = unpack2(d22a), fB = unpack2(d22b);
        float d12v[4] = {eA.x, eA.y, eB.x, eB.y};
        float d22v[4] = {fA.x, fA.y, fB.x, fB.y};
        float sp2[4];
#pragma unroll
        for (int j = 0; j < 4; j++) {
            float i2 = __fadd_rn(__fadd_rn(__fadd_rn(d12v[j], b12a[j]), d22v[j]), b12b[j]);
            b2[j] = __fadd_rn(__fmul_rn(r2[j], b2[j]), __fmul_rn(omr2[j], h2sp[j]));
            float B2 = __fadd_rn(B_J0, __fmul_rn(BETA, b2[j]));
            h2m[j] = __fsub_rn(__fadd_rn(__fmul_rn(h2m[j], a2[j]), __fmul_rn(oma2[j], i2)),
                               __fmul_rn(B2, h2sp[j]));
            sp2[j] = (__fsub_rn(h2m[j], B2) > 0.0f) ? 1.0f : 0.0f;
            s2c[j] += sp2[j];
        }

        unsigned F0 = __ballot_sync(0xffffffffu, sp2[0] != 0.0f);
        unsigned P0 = __ballot_sync(0xffffffffu, sp2[1] != 0.0f);
        unsigned F1 = __ballot_sync(0xffffffffu, sp2[2] != 0.0f);
        unsigned P1 = __ballot_sync(0xffffffffu, sp2[3] != 0.0f);
        {
            unsigned below = (1u << lane) - 1u;
            int base1 = __popc(F0) + __popc(P0);
            int c2 = base1 + __popc(F1) + __popc(P1);
            int c2np = (c2 + 3) & ~3;
            int rk0 = __popc(F0 & below) + __popc(P0 & below);
            int rk1 = rk0 + (int)((F0 >> lane) & 1u);
            int rk2 = base1 + __popc(F1 & below) + __popc(P1 & below);
            int rk3 = rk2 + (int)((F1 >> lane) & 1u);
            if (sp2[0] != 0.0f) L2[rk0] = h0;
            if (sp2[1] != 0.0f) L2[rk1] = h0 + 1;
            if (sp2[2] != 0.0f) L2[rk2] = h64;
            if (sp2[3] != 0.0f) L2[rk3] = h64 + 1;
            if (lane < c2np - c2) L2[c2 + lane] = 128;
            c2p = c2np;
        }
        __syncwarp();

        // ---- quad gather: d22(t+1) + d2o(t) over list2 ----
        ull n22a, n22b;
        float d2o;
        gather_p2(w22s, w2os, L2, c2p, h0, h64, oo, n22a, n22b, d2o);

        // ---- readout om update (softmax deferred) ----
        if (ro) {
            float io = __fadd_rn(d2o, bo);
            om = __fadd_rn(__fmul_rn(om, aoo), __fmul_rn(omao, io));
            om_out[((size_t)t * BT + grow) * OO + lane] = om;
        }

#pragma unroll
        for (int j = 0; j < 4; j++) { h1sp[j] = sp1[j]; h2sp[j] = sp2[j]; }
        d11a = n11a; d11b = n11b;
        d22a = n22a; d22b = n22b;
        xtA = xnA; xtB = xnB;
    }

    *(float2*)&out[OUT_OFF_S1 + grow * HH + h0] =
        make_float2(__fdiv_rn(s1c[0], (float)TT), __fdiv_rn(s1c[1], (float)TT));
    *(float2*)&out[OUT_OFF_S1 + grow * HH + h64] =
        make_float2(__fdiv_rn(s1c[2], (float)TT), __fdiv_rn(s1c[3], (float)TT));
    *(float2*)&out[OUT_OFF_S2 + grow * HH + h0] =
        make_float2(__fdiv_rn(s2c[0], (float)TT), __fdiv_rn(s2c[1], (float)TT));
    *(float2*)&out[OUT_OFF_S2 + grow * HH + h64] =
        make_float2(__fdiv_rn(s2c[2], (float)TT), __fdiv_rn(s2c[3], (float)TT));
}

// ---------------------------------------------------------------------------
// Kernel 2b: softmax + ascending-t accumulation per batch row.
// ---------------------------------------------------------------------------
__global__ __launch_bounds__(256) void softmax_acc_kernel(
    const float* __restrict__ om_in, float* __restrict__ out)
{
    __shared__ float sm[(TT - 11) * OO];
    const int b = blockIdx.x;
    const int wid = threadIdx.x >> 5;
    const int lane = threadIdx.x & 31;

    for (int t = 11 + wid; t < TT; t += 8) {
        float om = (lane < OO) ? om_in[((size_t)t * BT + b) * OO + lane] : 0.f;
        float v = (lane < OO) ? om : -3.4e38f;
#pragma unroll
        for (int d = 16; d; d >>= 1) v = fmaxf(v, __shfl_xor_sync(0xffffffffu, v, d));
        float e = (lane < OO) ? expf(__fsub_rn(om, v)) : 0.f;
        float ssum = e;
#pragma unroll
        for (int d = 16; d; d >>= 1) ssum += __shfl_xor_sync(0xffffffffu, ssum, d);
        if (lane < OO) sm[(t - 11) * OO + lane] = __fdiv_rn(e, ssum);
    }
    __syncthreads();

    if (threadIdx.x < OO) {
        float a = 0.f;
        for (int tt = 0; tt < TT - 11; tt++)
            a = __fadd_rn(a, sm[tt * OO + threadIdx.x]);
        out[OUT_OFF_ACC + b * OO + threadIdx.x] = a;
    }
}

// ---------------------------------------------------------------------------
// Kernel 3a/3b: A_norm (deterministic two-pass)
// ---------------------------------------------------------------------------
__global__ __launch_bounds__(256) void norm_part_kernel(
    const float* __restrict__ w11, const float* __restrict__ w22,
    const float* __restrict__ mask)
{
    __shared__ float red[256];
    int i = blockIdx.x * 256 + threadIdx.x;
    float s = fabsf(__fmul_rn(w11[i], mask[i]))
            + fabsf(__fmul_rn(w22[i], mask[16384 + i]));
    red[threadIdx.x] = s;
    __syncthreads();
    for (int d = 128; d > 0; d >>= 1) {
        if (threadIdx.x < d) red[threadIdx.x] += red[threadIdx.x + d];
        __syncthreads();
    }
    if (threadIdx.x == 0) g_npart[blockIdx.x] = red[0];
}

__global__ void norm_finish_kernel(float* __restrict__ out)
{
    int lane = threadIdx.x;
    __shared__ float w[2];
    float s = g_npart[lane];
#pragma unroll
    for (int d = 16; d; d >>= 1) s += __shfl_xor_sync(0xffffffffu, s, d);
    if ((lane & 31) == 0) w[lane >> 5] = s;
    __syncthreads();
    if (lane == 0) out[OUT_OFF_NORM] = w[0] + w[1];
}

// ---------------------------------------------------------------------------
extern "C" void kernel_launch(void* const* d_in, const int* in_sizes, int n_in,
                              void* d_out, int out_size)
{
    const float* x          = (const float*)d_in[0];
    const float* mask       = (const float*)d_in[1];
    const float* w_ih1      = (const float*)d_in[2];
    const float* b_ih1      = (const float*)d_in[3];
    const float* w_h1h1     = (const float*)d_in[4];
    const float* b_h1h1     = (const float*)d_in[5];
    const float* w_h1h2     = (const float*)d_in[6];
    const float* b_h1h2     = (const float*)d_in[7];
    const float* w_h2h2     = (const float*)d_in[8];
    const float* b_h2h2     = (const float*)d_in[9];
    const float* w_h2o      = (const float*)d_in[10];
    const float* b_h2o      = (const float*)d_in[11];
    const float* tau_adp_h1 = (const float*)d_in[12];
    const float* tau_adp_h2 = (const float*)d_in[13];
    const float* tau_m_h1   = (const float*)d_in[14];
    const float* tau_m_h2   = (const float*)d_in[15];
    const float* tau_m_o    = (const float*)d_in[16];
    const float* hid1_mem0  = (const float*)d_in[17];
    const float* hid2_mem0  = (const float*)d_in[18];
    const float* out_mem0   = (const float*)d_in[19];
    float* out = (float*)d_out;

    float* xin = nullptr;
    cudaGetSymbolAddress((void**)&xin, g_xin);
    float* omb = nullptr;
    cudaGetSymbolAddress((void**)&omb, g_om);

    cudaFuncSetAttribute(scan_kernel, cudaFuncAttributeMaxDynamicSharedMemorySize,
                         SCAN_SMEM_BYTES);

    gemm_xin_kernel<<<(BT * TT) / GTM, 256>>>(x, w_ih1, b_ih1, xin);
    scan_kernel<<<BT / ROWS_PER_CTA, 128, SCAN_SMEM_BYTES>>>(
        xin, mask, w_h1h1, b_h1h1, w_h1h2, b_h1h2, w_h2h2, b_h2h2,
        w_h2o, b_h2o, tau_adp_h1, tau_adp_h2, tau_m_h1, tau_m_h2, tau_m_o,
        hid1_mem0, hid2_mem0, out_mem0, omb, out);
    softmax_acc_kernel<<<BT, 256>>>(omb, out);
    norm_part_kernel<<<64, 256>>>(w_h1h1, w_h2h2, mask);
    norm_finish_kernel<<<1, 64>>>(out);
}